// round 1
// baseline (speedup 1.0000x reference)
#include <cuda_runtime.h>
#include <cstdint>
#include <math.h>

#define N_    64
#define C_    128
#define K_    64
#define P_    4096
#define ALPHA_ 50.0f
#define EPS_  1e-12f

// ---------------- scratch (no cudaMalloc allowed) ----------------
__device__ float g_Wn[C_ * K_];                      // column-normalized W  [c][k]
__device__ float g_invn[N_ * P_];                    // 1/max(||x||,eps) per (n,p)
__device__ float g_sa[N_ * K_ * P_];                 // softmax assignments [n][k][p]  (64MB)
__device__ float g_partial[N_ * 8 * K_ * C_];        // GEMM2 split partials [n][ps][k][c] (16MB)

// ---------------- f32x2 packed-FMA helpers ----------------
__device__ __forceinline__ unsigned long long pk2(float a, float b) {
    unsigned long long r;
    unsigned int x = __float_as_uint(a), y = __float_as_uint(b);
    asm("mov.b64 %0, {%1, %2};" : "=l"(r) : "r"(x), "r"(y));
    return r;
}
__device__ __forceinline__ void upk2(unsigned long long v, float& a, float& b) {
    unsigned int x, y;
    asm("mov.b64 {%0, %1}, %2;" : "=r"(x), "=r"(y) : "l"(v));
    a = __uint_as_float(x); b = __uint_as_float(y);
}
#define FMA2_(d, a, b) asm("fma.rn.f32x2 %0, %1, %2, %3;" : "=l"(d) : "l"(a), "l"(b), "l"(d))

// ---------------- kernel 0: column-normalize W ----------------
__global__ void wn_kernel(const float* __restrict__ W) {
    int k = threadIdx.x;                 // 64 threads
    float ss = 0.f;
    #pragma unroll 8
    for (int c = 0; c < C_; ++c) { float v = W[c * K_ + k]; ss = fmaf(v, v, ss); }
    float inv = 1.f / fmaxf(sqrtf(ss), EPS_);
    #pragma unroll 8
    for (int c = 0; c < C_; ++c) g_Wn[c * K_ + k] = W[c * K_ + k] * inv;
}

// ---------------- kernel B: logits GEMM + softmax ----------------
// grid (P/128, N), block 128. Thread owns one pixel, accumulates all 64 k.
__global__ __launch_bounds__(128) void kB(const float* __restrict__ x,
                                          const float* __restrict__ bias,
                                          float* __restrict__ logits_out) {
    __shared__ __align__(16) float wns[C_ * K_];   // 32KB
    __shared__ float bs[K_];

    const int tid = threadIdx.x;
    const int n   = blockIdx.y;
    const int p0  = blockIdx.x * 128;

    for (int i = tid; i < C_ * K_; i += 128) wns[i] = g_Wn[i];
    if (tid < K_) bs[tid] = bias[tid];
    __syncthreads();

    const float* xp = x + (size_t)n * C_ * P_ + p0 + tid;

    unsigned long long acc[32];
    #pragma unroll
    for (int j = 0; j < 32; ++j) acc[j] = 0ull;     // (0.f, 0.f)
    float ss = 0.f;

    #pragma unroll 4
    for (int c = 0; c < C_; ++c) {
        float v = xp[(size_t)c * P_];
        ss = fmaf(v, v, ss);
        unsigned long long vv = pk2(v, v);
        const ulonglong2* wr = (const ulonglong2*)(wns + c * K_);
        #pragma unroll
        for (int j = 0; j < 16; ++j) {
            ulonglong2 q = wr[j];
            FMA2_(acc[2 * j],     vv, q.x);
            FMA2_(acc[2 * j + 1], vv, q.y);
        }
    }

    float invn = 1.f / fmaxf(sqrtf(ss), EPS_);
    g_invn[n * P_ + p0 + tid] = invn;

    float lg[K_];
    #pragma unroll
    for (int j = 0; j < 32; ++j) upk2(acc[j], lg[2 * j], lg[2 * j + 1]);

    // write logits (einsum result, pre-bias/alpha) + find max of scaled logits
    float* lo = logits_out + (size_t)n * K_ * P_ + p0 + tid;
    float mx = -3.4e38f;
    #pragma unroll
    for (int k = 0; k < K_; ++k) {
        lg[k] *= invn;
        lo[(size_t)k * P_] = lg[k];
        float t = (lg[k] + bs[k]) * ALPHA_;
        mx = fmaxf(mx, t);
    }
    float sum = 0.f;
    #pragma unroll
    for (int k = 0; k < K_; ++k) {
        float e = __expf((lg[k] + bs[k]) * ALPHA_ - mx);
        lg[k] = e;
        sum += e;
    }
    float rs = 1.f / sum;
    float* so = g_sa + ((size_t)n * K_) * P_ + p0 + tid;
    #pragma unroll
    for (int k = 0; k < K_; ++k) so[(size_t)k * P_] = lg[k] * rs;
}

// ---------------- kernel C: VLAD GEMM (dot part), split over P ----------------
// grid (8 psplits, N), block 256. Thread tile: 4 k  x 8 c (4 f32x2 pairs).
#define XS_STRIDE 132            // 128 c + pad (4-way max write conflict, float4-aligned)
#define SA_STRIDE 65             // 64 p + pad
__global__ __launch_bounds__(256) void kC(const float* __restrict__ x) {
    extern __shared__ float smem[];
    float* xs  = smem;                        // [p=64][XS_STRIDE]  xf = x*invn
    float* sas = smem + 64 * XS_STRIDE;       // [k=64][SA_STRIDE]

    const int tid = threadIdx.x;
    const int n   = blockIdx.y;
    const int ps  = blockIdx.x;
    const int kg  = tid & 15;                 // k = kg*4 + kq
    const int cg  = tid >> 4;                 // c = cg*8 + j

    unsigned long long acc[4][4];
    #pragma unroll
    for (int a = 0; a < 4; ++a)
        #pragma unroll
        for (int b = 0; b < 4; ++b) acc[a][b] = 0ull;

    const int pl = tid & 63;
    const int qb = tid >> 6;                  // 0..3

    for (int t = 0; t < 8; ++t) {
        const int p0 = ps * 512 + t * 64;
        // ---- stage xf tile [p][c] and sa tile [k][p] ----
        float inv = g_invn[n * P_ + p0 + pl];
        const float* xb = x + (size_t)n * C_ * P_ + p0 + pl;
        #pragma unroll 8
        for (int i = 0; i < 32; ++i) {
            int c = qb + i * 4;
            xs[pl * XS_STRIDE + c] = xb[(size_t)c * P_] * inv;
        }
        const float* sb = g_sa + ((size_t)n * K_) * P_ + p0 + pl;
        #pragma unroll 8
        for (int i = 0; i < 16; ++i) {
            int k = qb + i * 4;
            sas[k * SA_STRIDE + pl] = sb[(size_t)k * P_];
        }
        __syncthreads();
        // ---- compute ----
        #pragma unroll 2
        for (int p = 0; p < 64; ++p) {
            const float4* xr = (const float4*)(xs + p * XS_STRIDE + cg * 8);
            float4 a4 = xr[0], b4 = xr[1];
            unsigned long long x0 = pk2(a4.x, a4.y), x1 = pk2(a4.z, a4.w);
            unsigned long long x2 = pk2(b4.x, b4.y), x3 = pk2(b4.z, b4.w);
            #pragma unroll
            for (int kq = 0; kq < 4; ++kq) {
                float s = sas[(kg * 4 + kq) * SA_STRIDE + p];
                unsigned long long s2 = pk2(s, s);
                FMA2_(acc[kq][0], s2, x0);
                FMA2_(acc[kq][1], s2, x1);
                FMA2_(acc[kq][2], s2, x2);
                FMA2_(acc[kq][3], s2, x3);
            }
        }
        __syncthreads();
    }

    float* pp = g_partial + ((size_t)(n * 8 + ps) * K_) * C_;
    #pragma unroll
    for (int kq = 0; kq < 4; ++kq) {
        int k = kg * 4 + kq;
        #pragma unroll
        for (int cp = 0; cp < 4; ++cp) {
            float u0, u1;
            upk2(acc[kq][cp], u0, u1);
            int c = cg * 8 + cp * 2;
            pp[k * C_ + c]     = u0;
            pp[k * C_ + c + 1] = u1;
        }
    }
}

// ---------------- kernel D: sasum + combine + subtract + intra-norm ----------------
// grid N*K blocks, 128 threads (one per c)
__global__ __launch_bounds__(128) void kD(const float* __restrict__ W,
                                          float* __restrict__ vlad_out) {
    __shared__ float red[128];
    const int b = blockIdx.x;
    const int n = b >> 6, k = b & 63, tid = threadIdx.x;

    // sum_p sa[n,k,p]
    const float* sp = g_sa + ((size_t)n * K_ + k) * P_;
    float s = 0.f;
    #pragma unroll 8
    for (int i = tid; i < P_; i += 128) s += sp[i];
    red[tid] = s; __syncthreads();
    #pragma unroll
    for (int o = 64; o > 0; o >>= 1) { if (tid < o) red[tid] += red[tid + o]; __syncthreads(); }
    float sasum = red[0];
    __syncthreads();

    float v = 0.f;
    #pragma unroll
    for (int ps = 0; ps < 8; ++ps)
        v += g_partial[((size_t)(n * 8 + ps) * K_ + k) * C_ + tid];
    v = fmaf(-sasum, W[tid * K_ + k], v);

    red[tid] = v * v; __syncthreads();
    #pragma unroll
    for (int o = 64; o > 0; o >>= 1) { if (tid < o) red[tid] += red[tid + o]; __syncthreads(); }
    float inv = 1.f / fmaxf(sqrtf(red[0]), EPS_);
    vlad_out[((size_t)n * K_ + k) * C_ + tid] = v * inv;
}

// ---------------- kernel E: global L2 per n, in place ----------------
__global__ __launch_bounds__(256) void kE(float* __restrict__ vlad) {
    __shared__ float red[256];
    const int n = blockIdx.x, tid = threadIdx.x;
    float* base = vlad + (size_t)n * K_ * C_;
    float v[32]; float ss = 0.f;
    #pragma unroll
    for (int i = 0; i < 32; ++i) { v[i] = base[tid + 256 * i]; ss = fmaf(v[i], v[i], ss); }
    red[tid] = ss; __syncthreads();
    #pragma unroll
    for (int o = 128; o > 0; o >>= 1) { if (tid < o) red[tid] += red[tid + o]; __syncthreads(); }
    float inv = 1.f / fmaxf(sqrtf(red[0]), EPS_);
    #pragma unroll
    for (int i = 0; i < 32; ++i) base[tid + 256 * i] = v[i] * inv;
}

// ---------------- launch ----------------
extern "C" void kernel_launch(void* const* d_in, const int* in_sizes, int n_in,
                              void* d_out, int out_size) {
    const float* x    = (const float*)d_in[0];   // [64,128,64,64]
    const float* W    = (const float*)d_in[1];   // [128,64]
    const float* bias = (const float*)d_in[2];   // [64]
    float* out        = (float*)d_out;
    float* vlad_out   = out;                               // [64, 64*128]
    float* logits_out = out + (size_t)N_ * K_ * C_;        // [64, 64, 4096]

    wn_kernel<<<1, 64>>>(W);

    dim3 gB(P_ / 128, N_);
    kB<<<gB, 128>>>(x, bias, logits_out);

    static bool attr_set = false;
    const int smemC = (64 * XS_STRIDE + 64 * SA_STRIDE) * (int)sizeof(float);
    if (!attr_set) {
        cudaFuncSetAttribute(kC, cudaFuncAttributeMaxDynamicSharedMemorySize, smemC);
        attr_set = true;
    }
    dim3 gC(8, N_);
    kC<<<gC, 256, smemC>>>(x);

    kD<<<N_ * K_, 128>>>(W, vlad_out);
    kE<<<N_, 256>>>(vlad_out);
}

// round 2
// speedup vs baseline: 1.0938x; 1.0938x over previous
#include <cuda_runtime.h>
#include <cstdint>
#include <math.h>

#define N_    64
#define C_    128
#define K_    64
#define P_    4096
#define ALPHA_ 50.0f
#define EPS_  1e-12f

// ---------------- scratch (no cudaMalloc allowed) ----------------
__device__ float g_Wn[C_ * K_];                 // column-normalized W [c][k]
__device__ float g_partial[N_ * 8 * K_ * C_];   // GEMM2 split partials [n][ps][k][c] (16MB)
__device__ float g_sasum[N_ * 8 * K_];          // sasum split partials [n][ps][k]

// ---------------- f32x2 packed-FMA helpers ----------------
__device__ __forceinline__ unsigned long long pk2(float a, float b) {
    unsigned long long r;
    unsigned int x = __float_as_uint(a), y = __float_as_uint(b);
    asm("mov.b64 %0, {%1, %2};" : "=l"(r) : "r"(x), "r"(y));
    return r;
}
__device__ __forceinline__ void upk2(unsigned long long v, float& a, float& b) {
    unsigned int x, y;
    asm("mov.b64 {%0, %1}, %2;" : "=r"(x), "=r"(y) : "l"(v));
    a = __uint_as_float(x); b = __uint_as_float(y);
}
#define FMA2_(d, a, b) asm("fma.rn.f32x2 %0, %1, %2, %3;" : "=l"(d) : "l"(a), "l"(b), "l"(d))

// ---------------- kernel 0: column-normalize W ----------------
__global__ void wn_kernel(const float* __restrict__ W) {
    int k = threadIdx.x;                 // 64 threads
    float ss = 0.f;
    #pragma unroll 8
    for (int c = 0; c < C_; ++c) { float v = W[c * K_ + k]; ss = fmaf(v, v, ss); }
    float inv = 1.f / fmaxf(sqrtf(ss), EPS_);
    #pragma unroll 8
    for (int c = 0; c < C_; ++c) g_Wn[c * K_ + k] = W[c * K_ + k] * inv;
}

// ---------------- fused mega kernel ----------------
// grid (8, 64): block handles (n = blockIdx.y, 512 pixels = blockIdx.x slice)
// 8 subtiles of 64 pixels:
//   load x tile [128c x 64p] -> smem (layout [c][p], stride 72)
//   per-pixel L2 normalize in smem
//   GEMM1 (logits = Wn^T xf) reg-tiled 4k x 4p  -> write logits, stage to sas
//   softmax over k (smem sas [p][k], stride 65)
//   sasum partial accumulation (deterministic ownership)
//   GEMM2 (sum_p sa*xf) reg-tiled 4k x 8c into persistent accumulators
// writes deterministic split partials at the end.
#define XF_STR 72
#define SA_STR 65

__global__ __launch_bounds__(256, 2) void kMega(const float* __restrict__ x,
                                                const float* __restrict__ bias,
                                                float* __restrict__ logits_out) {
    extern __shared__ float sm[];
    float* ws  = sm;                      // [c][k]      128*64 = 8192
    float* xf  = sm + C_ * K_;            // [c][XF_STR] 128*72 = 9216
    float* sas = xf + C_ * XF_STR;        // [p][SA_STR] 64*65  = 4160
    float* bs  = sas + 64 * SA_STR;       // [64]

    const int tid = threadIdx.x;
    const int n   = blockIdx.y;
    const int ps  = blockIdx.x;

    for (int i = tid; i < C_ * K_; i += 256) ws[i] = g_Wn[i];
    if (tid < 64) bs[tid] = bias[tid];

    // thread-role index splits
    const int pq   = tid & 15,  crow = tid >> 4;   // loader: p4=pq*4, c rows crow+16i
    const int pg   = tid & 15,  kg   = tid >> 4;   // GEMM1:  p=pg*4+., k=kg*4+.
    const int kg2  = tid & 15,  cg   = tid >> 4;   // GEMM2:  k=kg2*4+., c=cg*8+.
    const int pN   = tid >> 2,  qN   = tid & 3;    // normalize/softmax: pixel pN, quarter qN
    const int kS   = tid & 63,  part = tid >> 6;   // sasum ownership

    unsigned long long acc2[4][4];
    #pragma unroll
    for (int a = 0; a < 4; ++a)
        #pragma unroll
        for (int b = 0; b < 4; ++b) acc2[a][b] = 0ull;
    float sasum_reg = 0.f;

    const float* xbase = x + (size_t)n * C_ * P_ + ps * 512;
    float* lb = logits_out + (size_t)n * K_ * P_ + ps * 512;

    __syncthreads();   // ws, bs ready

    for (int sub = 0; sub < 8; ++sub) {
        const int p0 = sub * 64;

        // ---- load raw x tile (coalesced float4) ----
        {
            const float* xp = xbase + p0 + pq * 4;
            #pragma unroll
            for (int i = 0; i < 8; ++i) {
                int c = crow + 16 * i;
                float4 v = *(const float4*)(xp + (size_t)c * P_);
                *(float4*)(xf + c * XF_STR + pq * 4) = v;
            }
        }
        __syncthreads();

        // ---- per-pixel L2 normalize (4 threads per pixel, conflict-free banks) ----
        {
            float vals[32]; float ss = 0.f;
            #pragma unroll
            for (int i = 0; i < 32; ++i) {
                float v = xf[(qN + 4 * i) * XF_STR + pN];
                vals[i] = v; ss = fmaf(v, v, ss);
            }
            ss += __shfl_xor_sync(0xffffffffu, ss, 1);
            ss += __shfl_xor_sync(0xffffffffu, ss, 2);
            float inv = 1.f / fmaxf(sqrtf(ss), EPS_);
            #pragma unroll
            for (int i = 0; i < 32; ++i)
                xf[(qN + 4 * i) * XF_STR + pN] = vals[i] * inv;
        }
        __syncthreads();

        // ---- GEMM1: logits[4k x 4p] over 128 c ----
        {
            unsigned long long aA[4], aB[4];
            #pragma unroll
            for (int kq = 0; kq < 4; ++kq) { aA[kq] = 0ull; aB[kq] = 0ull; }

            #pragma unroll 8
            for (int c = 0; c < C_; ++c) {
                float4 w4 = *(const float4*)(ws + c * K_ + kg * 4);
                float4 x4 = *(const float4*)(xf + c * XF_STR + pg * 4);
                unsigned long long xlo = pk2(x4.x, x4.y);
                unsigned long long xhi = pk2(x4.z, x4.w);
                unsigned long long w0 = pk2(w4.x, w4.x);
                unsigned long long w1 = pk2(w4.y, w4.y);
                unsigned long long w2 = pk2(w4.z, w4.z);
                unsigned long long w3 = pk2(w4.w, w4.w);
                FMA2_(aA[0], w0, xlo); FMA2_(aB[0], w0, xhi);
                FMA2_(aA[1], w1, xlo); FMA2_(aB[1], w1, xhi);
                FMA2_(aA[2], w2, xlo); FMA2_(aB[2], w2, xhi);
                FMA2_(aA[3], w3, xlo); FMA2_(aB[3], w3, xhi);
            }

            // write sa_logits (coalesced float4) + stage into sas [p][k]
            #pragma unroll
            for (int kq = 0; kq < 4; ++kq) {
                float l0, l1, l2, l3;
                upk2(aA[kq], l0, l1);
                upk2(aB[kq], l2, l3);
                int k = kg * 4 + kq;
                *(float4*)(lb + (size_t)k * P_ + p0 + pg * 4) = make_float4(l0, l1, l2, l3);
                sas[(pg * 4 + 0) * SA_STR + k] = l0;
                sas[(pg * 4 + 1) * SA_STR + k] = l1;
                sas[(pg * 4 + 2) * SA_STR + k] = l2;
                sas[(pg * 4 + 3) * SA_STR + k] = l3;
            }
        }
        __syncthreads();

        // ---- softmax over k per pixel (4 threads per pixel) ----
        {
            float lv[16];
            float m = -3.4e38f;
            #pragma unroll
            for (int i = 0; i < 16; ++i) {
                int k = qN + 4 * i;
                float t = (sas[pN * SA_STR + k] + bs[k]) * ALPHA_;
                lv[i] = t; m = fmaxf(m, t);
            }
            m = fmaxf(m, __shfl_xor_sync(0xffffffffu, m, 1));
            m = fmaxf(m, __shfl_xor_sync(0xffffffffu, m, 2));
            float s = 0.f;
            #pragma unroll
            for (int i = 0; i < 16; ++i) {
                float e = __expf(lv[i] - m);
                lv[i] = e; s += e;
            }
            s += __shfl_xor_sync(0xffffffffu, s, 1);
            s += __shfl_xor_sync(0xffffffffu, s, 2);
            float rs = 1.f / s;
            #pragma unroll
            for (int i = 0; i < 16; ++i)
                sas[pN * SA_STR + qN + 4 * i] = lv[i] * rs;
        }
        __syncthreads();

        // ---- sasum partial (thread owns (part, k) -> deterministic) ----
        {
            float s = 0.f;
            #pragma unroll
            for (int i = 0; i < 16; ++i) s += sas[(part * 16 + i) * SA_STR + kS];
            sasum_reg += s;
        }

        // ---- GEMM2: acc2[4k x 8c] over 64 p ----
        {
            #pragma unroll 2
            for (int p = 0; p < 64; ++p) {
                float s0 = sas[p * SA_STR + kg2 * 4 + 0];
                float s1 = sas[p * SA_STR + kg2 * 4 + 1];
                float s2 = sas[p * SA_STR + kg2 * 4 + 2];
                float s3 = sas[p * SA_STR + kg2 * 4 + 3];
                float xv0 = xf[(cg * 8 + 0) * XF_STR + p];
                float xv1 = xf[(cg * 8 + 1) * XF_STR + p];
                float xv2 = xf[(cg * 8 + 2) * XF_STR + p];
                float xv3 = xf[(cg * 8 + 3) * XF_STR + p];
                float xv4 = xf[(cg * 8 + 4) * XF_STR + p];
                float xv5 = xf[(cg * 8 + 5) * XF_STR + p];
                float xv6 = xf[(cg * 8 + 6) * XF_STR + p];
                float xv7 = xf[(cg * 8 + 7) * XF_STR + p];
                unsigned long long xp0 = pk2(xv0, xv1);
                unsigned long long xp1 = pk2(xv2, xv3);
                unsigned long long xp2 = pk2(xv4, xv5);
                unsigned long long xp3 = pk2(xv6, xv7);
                unsigned long long sp;
                sp = pk2(s0, s0);
                FMA2_(acc2[0][0], sp, xp0); FMA2_(acc2[0][1], sp, xp1);
                FMA2_(acc2[0][2], sp, xp2); FMA2_(acc2[0][3], sp, xp3);
                sp = pk2(s1, s1);
                FMA2_(acc2[1][0], sp, xp0); FMA2_(acc2[1][1], sp, xp1);
                FMA2_(acc2[1][2], sp, xp2); FMA2_(acc2[1][3], sp, xp3);
                sp = pk2(s2, s2);
                FMA2_(acc2[2][0], sp, xp0); FMA2_(acc2[2][1], sp, xp1);
                FMA2_(acc2[2][2], sp, xp2); FMA2_(acc2[2][3], sp, xp3);
                sp = pk2(s3, s3);
                FMA2_(acc2[3][0], sp, xp0); FMA2_(acc2[3][1], sp, xp1);
                FMA2_(acc2[3][2], sp, xp2); FMA2_(acc2[3][3], sp, xp3);
            }
        }
        __syncthreads();   // before next subtile overwrites xf/sas
    }

    // ---- write GEMM2 split partials ----
    {
        float* pp = g_partial + ((size_t)(n * 8 + ps) * K_) * C_;
        #pragma unroll
        for (int kq = 0; kq < 4; ++kq) {
            int k = kg2 * 4 + kq;
            #pragma unroll
            for (int cp = 0; cp < 4; ++cp) {
                float u0, u1;
                upk2(acc2[kq][cp], u0, u1);
                *(float2*)(pp + k * C_ + cg * 8 + cp * 2) = make_float2(u0, u1);
            }
        }
    }

    // ---- reduce sasum parts and write ----
    sas[part * 64 + kS] = sasum_reg;
    __syncthreads();
    if (tid < 64)
        g_sasum[(n * 8 + ps) * 64 + tid] =
            sas[tid] + sas[64 + tid] + sas[128 + tid] + sas[192 + tid];
}

// ---------------- kernel D: combine partials + subtract + intra-norm ----------------
// grid N*K blocks, 128 threads (one per c)
__global__ __launch_bounds__(128) void kD(const float* __restrict__ W,
                                          float* __restrict__ vlad_out) {
    __shared__ float red[128];
    const int b = blockIdx.x;
    const int n = b >> 6, k = b & 63, tid = threadIdx.x;

    float sasum = 0.f;
    #pragma unroll
    for (int ps = 0; ps < 8; ++ps) sasum += g_sasum[(n * 8 + ps) * 64 + k];

    float v = 0.f;
    #pragma unroll
    for (int ps = 0; ps < 8; ++ps)
        v += g_partial[((size_t)(n * 8 + ps) * K_ + k) * C_ + tid];
    v = fmaf(-sasum, W[tid * K_ + k], v);

    red[tid] = v * v; __syncthreads();
    #pragma unroll
    for (int o = 64; o > 0; o >>= 1) { if (tid < o) red[tid] += red[tid + o]; __syncthreads(); }
    float inv = 1.f / fmaxf(sqrtf(red[0]), EPS_);
    vlad_out[((size_t)n * K_ + k) * C_ + tid] = v * inv;
}

// ---------------- kernel E: global L2 per n, in place ----------------
__global__ __launch_bounds__(256) void kE(float* __restrict__ vlad) {
    __shared__ float red[256];
    const int n = blockIdx.x, tid = threadIdx.x;
    float* base = vlad + (size_t)n * K_ * C_;
    float v[32]; float ss = 0.f;
    #pragma unroll
    for (int i = 0; i < 32; ++i) { v[i] = base[tid + 256 * i]; ss = fmaf(v[i], v[i], ss); }
    red[tid] = ss; __syncthreads();
    #pragma unroll
    for (int o = 128; o > 0; o >>= 1) { if (tid < o) red[tid] += red[tid + o]; __syncthreads(); }
    float inv = 1.f / fmaxf(sqrtf(red[0]), EPS_);
    #pragma unroll
    for (int i = 0; i < 32; ++i) base[tid + 256 * i] = v[i] * inv;
}

// ---------------- launch ----------------
extern "C" void kernel_launch(void* const* d_in, const int* in_sizes, int n_in,
                              void* d_out, int out_size) {
    const float* x    = (const float*)d_in[0];   // [64,128,64,64]
    const float* W    = (const float*)d_in[1];   // [128,64]
    const float* bias = (const float*)d_in[2];   // [64]
    float* out        = (float*)d_out;
    float* vlad_out   = out;                               // [64, 64*128]
    float* logits_out = out + (size_t)N_ * K_ * C_;        // [64, 64, 4096]

    const int smemM = (C_ * K_ + C_ * XF_STR + 64 * SA_STR + 64) * (int)sizeof(float);
    static bool attr_set = false;
    if (!attr_set) {
        cudaFuncSetAttribute(kMega, cudaFuncAttributeMaxDynamicSharedMemorySize, smemM);
        attr_set = true;
    }

    wn_kernel<<<1, 64>>>(W);

    dim3 gM(8, N_);
    kMega<<<gM, 256, smemM>>>(x, bias, logits_out);

    kD<<<N_ * K_, 128>>>(W, vlad_out);
    kE<<<N_, 256>>>(vlad_out);
}

// round 3
// speedup vs baseline: 1.0975x; 1.0034x over previous
#include <cuda_runtime.h>
#include <cstdint>
#include <math.h>

#define N_    64
#define C_    128
#define K_    64
#define P_    4096
#define ALPHA_ 50.0f
#define EPS_  1e-12f

// ---------------- scratch (no cudaMalloc allowed) ----------------
__device__ float g_Wn[C_ * K_];                 // column-normalized W [c][k]
__device__ float g_partial[N_ * 8 * K_ * C_];   // GEMM2 split partials [n][ps][k][c] (16MB)
__device__ float g_sasum[N_ * 8 * K_];          // sasum split partials [n][ps][k]

// ---------------- f32x2 packed-FMA helpers ----------------
__device__ __forceinline__ unsigned long long pk2(float a, float b) {
    unsigned long long r;
    unsigned int x = __float_as_uint(a), y = __float_as_uint(b);
    asm("mov.b64 %0, {%1, %2};" : "=l"(r) : "r"(x), "r"(y));
    return r;
}
__device__ __forceinline__ void upk2(unsigned long long v, float& a, float& b) {
    unsigned int x, y;
    asm("mov.b64 {%0, %1}, %2;" : "=r"(x), "=r"(y) : "l"(v));
    a = __uint_as_float(x); b = __uint_as_float(y);
}
#define FMA2_(d, a, b) asm("fma.rn.f32x2 %0, %1, %2, %3;" : "=l"(d) : "l"(a), "l"(b), "l"(d))

// ---------------- kernel 0: column-normalize W ----------------
__global__ void wn_kernel(const float* __restrict__ W) {
    int k = threadIdx.x;                 // 64 threads
    float ss = 0.f;
    #pragma unroll 8
    for (int c = 0; c < C_; ++c) { float v = W[c * K_ + k]; ss = fmaf(v, v, ss); }
    float inv = 1.f / fmaxf(sqrtf(ss), EPS_);
    #pragma unroll 8
    for (int c = 0; c < C_; ++c) g_Wn[c * K_ + k] = W[c * K_ + k] * inv;
}

// ---------------- fused mega kernel ----------------
// grid (8, 64): block handles (n = blockIdx.y, 512 pixels = blockIdx.x slice)
// 8 subtiles of 64 pixels:
//   load x tile [128c x 64p] -> smem (layout [c][p], stride 72)
//   per-pixel L2 normalize in smem
//   GEMM1 (logits = Wn^T xf) reg-tiled 4k x 4p  -> write logits, stage to sas
//   softmax over k (smem sas [p][k], stride 65)
//   sasum partial accumulation (deterministic ownership)
//   GEMM2 (sum_p sa*xf) reg-tiled 4k x 8c into persistent accumulators
// writes deterministic split partials at the end.
#define XF_STR 72
#define SA_STR 65

__global__ __launch_bounds__(256, 2) void kMega(const float* __restrict__ x,
                                                const float* __restrict__ bias,
                                                float* __restrict__ logits_out) {
    extern __shared__ float sm[];
    float* ws  = sm;                      // [c][k]      128*64 = 8192
    float* xf  = sm + C_ * K_;            // [c][XF_STR] 128*72 = 9216
    float* sas = xf + C_ * XF_STR;        // [p][SA_STR] 64*65  = 4160
    float* bs  = sas + 64 * SA_STR;       // [64]

    const int tid = threadIdx.x;
    const int n   = blockIdx.y;
    const int ps  = blockIdx.x;

    for (int i = tid; i < C_ * K_; i += 256) ws[i] = g_Wn[i];
    if (tid < 64) bs[tid] = bias[tid];

    // thread-role index splits
    const int pq   = tid & 15,  crow = tid >> 4;   // loader: p4=pq*4, c rows crow+16i
    const int pg   = tid & 15,  kg   = tid >> 4;   // GEMM1:  p=pg*4+., k=kg*4+.
    const int kg2  = tid & 15,  cg   = tid >> 4;   // GEMM2:  k=kg2*4+., c=cg*8+.
    const int pN   = tid >> 2,  qN   = tid & 3;    // normalize/softmax: pixel pN, quarter qN
    const int kS   = tid & 63,  part = tid >> 6;   // sasum ownership

    unsigned long long acc2[4][4];
    #pragma unroll
    for (int a = 0; a < 4; ++a)
        #pragma unroll
        for (int b = 0; b < 4; ++b) acc2[a][b] = 0ull;
    float sasum_reg = 0.f;

    const float* xbase = x + (size_t)n * C_ * P_ + ps * 512;
    float* lb = logits_out + (size_t)n * K_ * P_ + ps * 512;

    __syncthreads();   // ws, bs ready

    for (int sub = 0; sub < 8; ++sub) {
        const int p0 = sub * 64;

        // ---- load raw x tile (coalesced float4) ----
        {
            const float* xp = xbase + p0 + pq * 4;
            #pragma unroll
            for (int i = 0; i < 8; ++i) {
                int c = crow + 16 * i;
                float4 v = *(const float4*)(xp + (size_t)c * P_);
                *(float4*)(xf + c * XF_STR + pq * 4) = v;
            }
        }
        __syncthreads();

        // ---- per-pixel L2 normalize (4 threads per pixel, conflict-free banks) ----
        {
            float vals[32]; float ss = 0.f;
            #pragma unroll
            for (int i = 0; i < 32; ++i) {
                float v = xf[(qN + 4 * i) * XF_STR + pN];
                vals[i] = v; ss = fmaf(v, v, ss);
            }
            ss += __shfl_xor_sync(0xffffffffu, ss, 1);
            ss += __shfl_xor_sync(0xffffffffu, ss, 2);
            float inv = 1.f / fmaxf(sqrtf(ss), EPS_);
            #pragma unroll
            for (int i = 0; i < 32; ++i)
                xf[(qN + 4 * i) * XF_STR + pN] = vals[i] * inv;
        }
        __syncthreads();

        // ---- GEMM1: logits[4k x 4p] over 128 c ----
        {
            unsigned long long aA[4], aB[4];
            #pragma unroll
            for (int kq = 0; kq < 4; ++kq) { aA[kq] = 0ull; aB[kq] = 0ull; }

            #pragma unroll 8
            for (int c = 0; c < C_; ++c) {
                float4 w4 = *(const float4*)(ws + c * K_ + kg * 4);
                float4 x4 = *(const float4*)(xf + c * XF_STR + pg * 4);
                unsigned long long xlo = pk2(x4.x, x4.y);
                unsigned long long xhi = pk2(x4.z, x4.w);
                unsigned long long w0 = pk2(w4.x, w4.x);
                unsigned long long w1 = pk2(w4.y, w4.y);
                unsigned long long w2 = pk2(w4.z, w4.z);
                unsigned long long w3 = pk2(w4.w, w4.w);
                FMA2_(aA[0], w0, xlo); FMA2_(aB[0], w0, xhi);
                FMA2_(aA[1], w1, xlo); FMA2_(aB[1], w1, xhi);
                FMA2_(aA[2], w2, xlo); FMA2_(aB[2], w2, xhi);
                FMA2_(aA[3], w3, xlo); FMA2_(aB[3], w3, xhi);
            }

            // write sa_logits (coalesced float4) + stage into sas [p][k]
            #pragma unroll
            for (int kq = 0; kq < 4; ++kq) {
                float l0, l1, l2, l3;
                upk2(aA[kq], l0, l1);
                upk2(aB[kq], l2, l3);
                int k = kg * 4 + kq;
                *(float4*)(lb + (size_t)k * P_ + p0 + pg * 4) = make_float4(l0, l1, l2, l3);
                sas[(pg * 4 + 0) * SA_STR + k] = l0;
                sas[(pg * 4 + 1) * SA_STR + k] = l1;
                sas[(pg * 4 + 2) * SA_STR + k] = l2;
                sas[(pg * 4 + 3) * SA_STR + k] = l3;
            }
        }
        __syncthreads();

        // ---- softmax over k per pixel (4 threads per pixel) ----
        {
            float lv[16];
            float m = -3.4e38f;
            #pragma unroll
            for (int i = 0; i < 16; ++i) {
                int k = qN + 4 * i;
                float t = (sas[pN * SA_STR + k] + bs[k]) * ALPHA_;
                lv[i] = t; m = fmaxf(m, t);
            }
            m = fmaxf(m, __shfl_xor_sync(0xffffffffu, m, 1));
            m = fmaxf(m, __shfl_xor_sync(0xffffffffu, m, 2));
            float s = 0.f;
            #pragma unroll
            for (int i = 0; i < 16; ++i) {
                float e = __expf(lv[i] - m);
                lv[i] = e; s += e;
            }
            s += __shfl_xor_sync(0xffffffffu, s, 1);
            s += __shfl_xor_sync(0xffffffffu, s, 2);
            float rs = 1.f / s;
            #pragma unroll
            for (int i = 0; i < 16; ++i)
                sas[pN * SA_STR + qN + 4 * i] = lv[i] * rs;
        }
        __syncthreads();

        // ---- sasum partial (thread owns (part, k) -> deterministic) ----
        {
            float s = 0.f;
            #pragma unroll
            for (int i = 0; i < 16; ++i) s += sas[(part * 16 + i) * SA_STR + kS];
            sasum_reg += s;
        }

        // ---- GEMM2: acc2[4k x 8c] over 64 p ----
        {
            #pragma unroll 2
            for (int p = 0; p < 64; ++p) {
                float s0 = sas[p * SA_STR + kg2 * 4 + 0];
                float s1 = sas[p * SA_STR + kg2 * 4 + 1];
                float s2 = sas[p * SA_STR + kg2 * 4 + 2];
                float s3 = sas[p * SA_STR + kg2 * 4 + 3];
                float xv0 = xf[(cg * 8 + 0) * XF_STR + p];
                float xv1 = xf[(cg * 8 + 1) * XF_STR + p];
                float xv2 = xf[(cg * 8 + 2) * XF_STR + p];
                float xv3 = xf[(cg * 8 + 3) * XF_STR + p];
                float xv4 = xf[(cg * 8 + 4) * XF_STR + p];
                float xv5 = xf[(cg * 8 + 5) * XF_STR + p];
                float xv6 = xf[(cg * 8 + 6) * XF_STR + p];
                float xv7 = xf[(cg * 8 + 7) * XF_STR + p];
                unsigned long long xp0 = pk2(xv0, xv1);
                unsigned long long xp1 = pk2(xv2, xv3);
                unsigned long long xp2 = pk2(xv4, xv5);
                unsigned long long xp3 = pk2(xv6, xv7);
                unsigned long long sp;
                sp = pk2(s0, s0);
                FMA2_(acc2[0][0], sp, xp0); FMA2_(acc2[0][1], sp, xp1);
                FMA2_(acc2[0][2], sp, xp2); FMA2_(acc2[0][3], sp, xp3);
                sp = pk2(s1, s1);
                FMA2_(acc2[1][0], sp, xp0); FMA2_(acc2[1][1], sp, xp1);
                FMA2_(acc2[1][2], sp, xp2); FMA2_(acc2[1][3], sp, xp3);
                sp = pk2(s2, s2);
                FMA2_(acc2[2][0], sp, xp0); FMA2_(acc2[2][1], sp, xp1);
                FMA2_(acc2[2][2], sp, xp2); FMA2_(acc2[2][3], sp, xp3);
                sp = pk2(s3, s3);
                FMA2_(acc2[3][0], sp, xp0); FMA2_(acc2[3][1], sp, xp1);
                FMA2_(acc2[3][2], sp, xp2); FMA2_(acc2[3][3], sp, xp3);
            }
        }
        __syncthreads();   // before next subtile overwrites xf/sas
    }

    // ---- write GEMM2 split partials ----
    {
        float* pp = g_partial + ((size_t)(n * 8 + ps) * K_) * C_;
        #pragma unroll
        for (int kq = 0; kq < 4; ++kq) {
            int k = kg2 * 4 + kq;
            #pragma unroll
            for (int cp = 0; cp < 4; ++cp) {
                float u0, u1;
                upk2(acc2[kq][cp], u0, u1);
                *(float2*)(pp + k * C_ + cg * 8 + cp * 2) = make_float2(u0, u1);
            }
        }
    }

    // ---- reduce sasum parts and write ----
    sas[part * 64 + kS] = sasum_reg;
    __syncthreads();
    if (tid < 64)
        g_sasum[(n * 8 + ps) * 64 + tid] =
            sas[tid] + sas[64 + tid] + sas[128 + tid] + sas[192 + tid];
}

// ---------------- kernel D: combine partials + subtract + intra-norm ----------------
// grid N*K blocks, 128 threads (one per c)
__global__ __launch_bounds__(128) void kD(const float* __restrict__ W,
                                          float* __restrict__ vlad_out) {
    __shared__ float red[128];
    const int b = blockIdx.x;
    const int n = b >> 6, k = b & 63, tid = threadIdx.x;

    float sasum = 0.f;
    #pragma unroll
    for (int ps = 0; ps < 8; ++ps) sasum += g_sasum[(n * 8 + ps) * 64 + k];

    float v = 0.f;
    #pragma unroll
    for (int ps = 0; ps < 8; ++ps)
        v += g_partial[((size_t)(n * 8 + ps) * K_ + k) * C_ + tid];
    v = fmaf(-sasum, W[tid * K_ + k], v);

    red[tid] = v * v; __syncthreads();
    #pragma unroll
    for (int o = 64; o > 0; o >>= 1) { if (tid < o) red[tid] += red[tid + o]; __syncthreads(); }
    float inv = 1.f / fmaxf(sqrtf(red[0]), EPS_);
    vlad_out[((size_t)n * K_ + k) * C_ + tid] = v * inv;
}

// ---------------- kernel E: global L2 per n, in place ----------------
__global__ __launch_bounds__(256) void kE(float* __restrict__ vlad) {
    __shared__ float red[256];
    const int n = blockIdx.x, tid = threadIdx.x;
    float* base = vlad + (size_t)n * K_ * C_;
    float v[32]; float ss = 0.f;
    #pragma unroll
    for (int i = 0; i < 32; ++i) { v[i] = base[tid + 256 * i]; ss = fmaf(v[i], v[i], ss); }
    red[tid] = ss; __syncthreads();
    #pragma unroll
    for (int o = 128; o > 0; o >>= 1) { if (tid < o) red[tid] += red[tid + o]; __syncthreads(); }
    float inv = 1.f / fmaxf(sqrtf(red[0]), EPS_);
    #pragma unroll
    for (int i = 0; i < 32; ++i) base[tid + 256 * i] = v[i] * inv;
}

// ---------------- launch ----------------
extern "C" void kernel_launch(void* const* d_in, const int* in_sizes, int n_in,
                              void* d_out, int out_size) {
    const float* x    = (const float*)d_in[0];   // [64,128,64,64]
    const float* W    = (const float*)d_in[1];   // [128,64]
    const float* bias = (const float*)d_in[2];   // [64]
    float* out        = (float*)d_out;
    float* vlad_out   = out;                               // [64, 64*128]
    float* logits_out = out + (size_t)N_ * K_ * C_;        // [64, 64, 4096]

    const int smemM = (C_ * K_ + C_ * XF_STR + 64 * SA_STR + 64) * (int)sizeof(float);
    static bool attr_set = false;
    if (!attr_set) {
        cudaFuncSetAttribute(kMega, cudaFuncAttributeMaxDynamicSharedMemorySize, smemM);
        attr_set = true;
    }

    wn_kernel<<<1, 64>>>(W);

    dim3 gM(8, N_);
    kMega<<<gM, 256, smemM>>>(x, bias, logits_out);

    kD<<<N_ * K_, 128>>>(W, vlad_out);
    kE<<<N_, 256>>>(vlad_out);
}

// round 4
// speedup vs baseline: 1.2653x; 1.1528x over previous
#include <cuda_runtime.h>
#include <cstdint>
#include <math.h>

#define N_    64
#define C_    128
#define K_    64
#define P_    4096
#define ALPHA_ 50.0f
#define EPS_  1e-12f

typedef unsigned long long ull;

// ---------------- scratch ----------------
__device__ float g_Wn[C_ * K_];
__device__ float g_partial[N_ * 8 * K_ * C_];   // [n][ps][k][c]
__device__ float g_sasum[N_ * 8 * K_];          // [n][ps][k]

// ---------------- f32x2 helpers ----------------
__device__ __forceinline__ ull pk2(float a, float b) {
    ull r;
    asm("mov.b64 %0, {%1, %2};" : "=l"(r) : "r"(__float_as_uint(a)), "r"(__float_as_uint(b)));
    return r;
}
__device__ __forceinline__ void upk2(ull v, float& a, float& b) {
    unsigned int x, y;
    asm("mov.b64 {%0, %1}, %2;" : "=r"(x), "=r"(y) : "l"(v));
    a = __uint_as_float(x); b = __uint_as_float(y);
}
#define FMA2_(d, a, b) asm("fma.rn.f32x2 %0, %1, %2, %3;" : "=l"(d) : "l"(a), "l"(b), "l"(d))

// ---------------- kernel 0: column-normalize W ----------------
__global__ void wn_kernel(const float* __restrict__ W) {
    int k = threadIdx.x;
    float ss = 0.f;
    #pragma unroll 8
    for (int c = 0; c < C_; ++c) { float v = W[c * K_ + k]; ss = fmaf(v, v, ss); }
    float inv = 1.f / fmaxf(sqrtf(ss), EPS_);
    #pragma unroll 8
    for (int c = 0; c < C_; ++c) g_Wn[c * K_ + k] = W[c * K_ + k] * inv;
}

// ---------------- fused mega kernel ----------------
#define XF_STR 68
#define SA_STR 68

__global__ __launch_bounds__(256, 2) void kMega(const float* __restrict__ x,
                                                const float* __restrict__ bias,
                                                float* __restrict__ logits_out) {
    extern __shared__ float sm[];
    float* ws  = sm;                       // [c][k]      8192
    float* xf  = sm + C_ * K_;             // [c][XF_STR] 8704
    float* sas = xf + C_ * XF_STR;         // [k][SA_STR] 4352
    float* bs  = sas + K_ * SA_STR;        // [64]

    const int tid = threadIdx.x;
    const int n   = blockIdx.y;
    const int ps  = blockIdx.x;

    for (int i = tid; i < C_ * K_; i += 256) ws[i] = g_Wn[i];
    if (tid < 64) bs[tid] = bias[tid];

    const int pq  = tid & 15, cq = tid >> 4;   // loader
    const int pg  = tid & 15, kg = tid >> 4;   // GEMM1
    const int kg2 = tid & 15, cg = tid >> 4;   // GEMM2: k = kg2 + 16*kq, c = cg*8+m
    const int pN  = tid >> 2, qN = tid & 3;    // normalize / softmax
    const int kS  = tid & 63, part = tid >> 6; // sasum

    ull acc2[4][8];
    #pragma unroll
    for (int a = 0; a < 4; ++a)
        #pragma unroll
        for (int b = 0; b < 8; ++b) acc2[a][b] = 0ull;
    float sasum_reg = 0.f;

    const float* xbase = x + (size_t)n * C_ * P_ + ps * 512;
    float* lb = logits_out + (size_t)n * K_ * P_ + ps * 512;

    __syncthreads();

    for (int sub = 0; sub < 8; ++sub) {
        const int p0 = sub * 64;

        // ---- load raw x tile [c][p] (coalesced float4) ----
        {
            const float* xp = xbase + p0 + pq * 4;
            #pragma unroll
            for (int i = 0; i < 8; ++i) {
                int c = cq + 16 * i;
                float4 v = *(const float4*)(xp + (size_t)c * P_);
                *(float4*)(xf + c * XF_STR + pq * 4) = v;
            }
        }
        __syncthreads();

        // ---- per-pixel L2 normalize in place (4 threads / pixel) ----
        {
            float vals[32]; float ss = 0.f;
            #pragma unroll
            for (int i = 0; i < 32; ++i) {
                float v = xf[(qN + 4 * i) * XF_STR + pN];
                vals[i] = v; ss = fmaf(v, v, ss);
            }
            ss += __shfl_xor_sync(0xffffffffu, ss, 1);
            ss += __shfl_xor_sync(0xffffffffu, ss, 2);
            float inv = 1.f / fmaxf(sqrtf(ss), EPS_);
            #pragma unroll
            for (int i = 0; i < 32; ++i)
                xf[(qN + 4 * i) * XF_STR + pN] = vals[i] * inv;
        }
        __syncthreads();

        // ---- GEMM1: logits[4k x 4p], acc packed over p-pairs ----
        {
            ull a0[4], a1[4];
            #pragma unroll
            for (int kq = 0; kq < 4; ++kq) { a0[kq] = 0ull; a1[kq] = 0ull; }

            #pragma unroll 4
            for (int c = 0; c < C_; ++c) {
                ulonglong2 xp2 = *(const ulonglong2*)(xf + c * XF_STR + pg * 4);
                float4 w4 = *(const float4*)(ws + c * K_ + kg * 4);
                ull w;
                w = pk2(w4.x, w4.x); FMA2_(a0[0], w, xp2.x); FMA2_(a1[0], w, xp2.y);
                w = pk2(w4.y, w4.y); FMA2_(a0[1], w, xp2.x); FMA2_(a1[1], w, xp2.y);
                w = pk2(w4.z, w4.z); FMA2_(a0[2], w, xp2.x); FMA2_(a1[2], w, xp2.y);
                w = pk2(w4.w, w4.w); FMA2_(a0[3], w, xp2.x); FMA2_(a1[3], w, xp2.y);
            }

            #pragma unroll
            for (int kq = 0; kq < 4; ++kq) {
                float l0, l1, l2, l3;
                upk2(a0[kq], l0, l1);
                upk2(a1[kq], l2, l3);
                int k = kg * 4 + kq;
                float4 v4 = make_float4(l0, l1, l2, l3);
                *(float4*)(lb + (size_t)k * P_ + p0 + pg * 4) = v4;
                *(float4*)(sas + k * SA_STR + pg * 4) = v4;
            }
        }
        __syncthreads();

        // ---- softmax over k per pixel (4 threads / pixel), in place on sas ----
        {
            float lv[16];
            float m = -3.4e38f;
            #pragma unroll
            for (int i = 0; i < 16; ++i) {
                int k = qN + 4 * i;
                float t = (sas[k * SA_STR + pN] + bs[k]) * ALPHA_;
                lv[i] = t; m = fmaxf(m, t);
            }
            m = fmaxf(m, __shfl_xor_sync(0xffffffffu, m, 1));
            m = fmaxf(m, __shfl_xor_sync(0xffffffffu, m, 2));
            float s = 0.f;
            #pragma unroll
            for (int i = 0; i < 16; ++i) {
                float e = __expf(lv[i] - m);
                lv[i] = e; s += e;
            }
            s += __shfl_xor_sync(0xffffffffu, s, 1);
            s += __shfl_xor_sync(0xffffffffu, s, 2);
            float rs = 1.f / s;
            #pragma unroll
            for (int i = 0; i < 16; ++i)
                sas[(qN + 4 * i) * SA_STR + pN] = lv[i] * rs;
        }
        __syncthreads();

        // ---- sasum partial (thread owns (part, k)) ----
        {
            float s = 0.f;
            #pragma unroll
            for (int i = 0; i < 16; ++i) s += sas[kS * SA_STR + part * 16 + i];
            sasum_reg += s;
        }

        // ---- GEMM2: acc2[4k x 8c] packed over p-parity, 32 p-pairs ----
        {
            #pragma unroll 2
            for (int j = 0; j < 32; ++j) {
                ull s0 = *(const ull*)(sas + (kg2 +  0) * SA_STR + 2 * j);
                ull s1 = *(const ull*)(sas + (kg2 + 16) * SA_STR + 2 * j);
                ull s2 = *(const ull*)(sas + (kg2 + 32) * SA_STR + 2 * j);
                ull s3 = *(const ull*)(sas + (kg2 + 48) * SA_STR + 2 * j);
                ull xv0 = *(const ull*)(xf + (cg * 8 + 0) * XF_STR + 2 * j);
                ull xv1 = *(const ull*)(xf + (cg * 8 + 1) * XF_STR + 2 * j);
                ull xv2 = *(const ull*)(xf + (cg * 8 + 2) * XF_STR + 2 * j);
                ull xv3 = *(const ull*)(xf + (cg * 8 + 3) * XF_STR + 2 * j);
                ull xv4 = *(const ull*)(xf + (cg * 8 + 4) * XF_STR + 2 * j);
                ull xv5 = *(const ull*)(xf + (cg * 8 + 5) * XF_STR + 2 * j);
                ull xv6 = *(const ull*)(xf + (cg * 8 + 6) * XF_STR + 2 * j);
                ull xv7 = *(const ull*)(xf + (cg * 8 + 7) * XF_STR + 2 * j);
                FMA2_(acc2[0][0], s0, xv0); FMA2_(acc2[0][1], s0, xv1);
                FMA2_(acc2[0][2], s0, xv2); FMA2_(acc2[0][3], s0, xv3);
                FMA2_(acc2[0][4], s0, xv4); FMA2_(acc2[0][5], s0, xv5);
                FMA2_(acc2[0][6], s0, xv6); FMA2_(acc2[0][7], s0, xv7);
                FMA2_(acc2[1][0], s1, xv0); FMA2_(acc2[1][1], s1, xv1);
                FMA2_(acc2[1][2], s1, xv2); FMA2_(acc2[1][3], s1, xv3);
                FMA2_(acc2[1][4], s1, xv4); FMA2_(acc2[1][5], s1, xv5);
                FMA2_(acc2[1][6], s1, xv6); FMA2_(acc2[1][7], s1, xv7);
                FMA2_(acc2[2][0], s2, xv0); FMA2_(acc2[2][1], s2, xv1);
                FMA2_(acc2[2][2], s2, xv2); FMA2_(acc2[2][3], s2, xv3);
                FMA2_(acc2[2][4], s2, xv4); FMA2_(acc2[2][5], s2, xv5);
                FMA2_(acc2[2][6], s2, xv6); FMA2_(acc2[2][7], s2, xv7);
                FMA2_(acc2[3][0], s3, xv0); FMA2_(acc2[3][1], s3, xv1);
                FMA2_(acc2[3][2], s3, xv2); FMA2_(acc2[3][3], s3, xv3);
                FMA2_(acc2[3][4], s3, xv4); FMA2_(acc2[3][5], s3, xv5);
                FMA2_(acc2[3][6], s3, xv6); FMA2_(acc2[3][7], s3, xv7);
            }
        }
        __syncthreads();
    }

    // ---- write GEMM2 split partials (fold p-parity halves) ----
    {
        float* pp = g_partial + ((size_t)(n * 8 + ps) * K_) * C_;
        #pragma unroll
        for (int kq = 0; kq < 4; ++kq) {
            int k = kg2 + 16 * kq;
            #pragma unroll
            for (int m = 0; m < 8; ++m) {
                float u0, u1;
                upk2(acc2[kq][m], u0, u1);
                pp[k * C_ + cg * 8 + m] = u0 + u1;
            }
        }
    }

    // ---- reduce sasum parts (sas is free after last sync) ----
    sas[part * 64 + kS] = sasum_reg;
    __syncthreads();
    if (tid < 64)
        g_sasum[(n * 8 + ps) * 64 + tid] =
            sas[tid] + sas[64 + tid] + sas[128 + tid] + sas[192 + tid];
}

// ---------------- kernel D: combine + subtract + intra-norm + global/8 ----------------
__global__ __launch_bounds__(128) void kD(const float* __restrict__ W,
                                          float* __restrict__ vlad_out) {
    __shared__ float red[128];
    const int b = blockIdx.x;
    const int n = b >> 6, k = b & 63, tid = threadIdx.x;

    float sasum = 0.f;
    #pragma unroll
    for (int ps = 0; ps < 8; ++ps) sasum += g_sasum[(n * 8 + ps) * 64 + k];

    float v = 0.f;
    #pragma unroll
    for (int ps = 0; ps < 8; ++ps)
        v += g_partial[((size_t)(n * 8 + ps) * K_ + k) * C_ + tid];
    v = fmaf(-sasum, W[tid * K_ + k], v);

    red[tid] = v * v; __syncthreads();
    #pragma unroll
    for (int o = 64; o > 0; o >>= 1) { if (tid < o) red[tid] += red[tid + o]; __syncthreads(); }
    // intra-norm, then global L2 over 64 unit-norm rows is exactly sqrt(64)=8
    float inv = 0.125f / fmaxf(sqrtf(red[0]), EPS_);
    vlad_out[((size_t)n * K_ + k) * C_ + tid] = v * inv;
}

// ---------------- launch ----------------
extern "C" void kernel_launch(void* const* d_in, const int* in_sizes, int n_in,
                              void* d_out, int out_size) {
    const float* x    = (const float*)d_in[0];
    const float* W    = (const float*)d_in[1];
    const float* bias = (const float*)d_in[2];
    float* out        = (float*)d_out;
    float* vlad_out   = out;                               // [64, 8192]
    float* logits_out = out + (size_t)N_ * K_ * C_;        // [64, 64, 4096]

    const int smemM = (C_ * K_ + C_ * XF_STR + K_ * SA_STR + 64) * (int)sizeof(float);
    static bool attr_set = false;
    if (!attr_set) {
        cudaFuncSetAttribute(kMega, cudaFuncAttributeMaxDynamicSharedMemorySize, smemM);
        attr_set = true;
    }

    wn_kernel<<<1, 64>>>(W);

    dim3 gM(8, N_);
    kMega<<<gM, 256, smemM>>>(x, bias, logits_out);

    kD<<<N_ * K_, 128>>>(W, vlad_out);
}

// round 5
// speedup vs baseline: 1.3065x; 1.0325x over previous
#include <cuda_runtime.h>
#include <cstdint>
#include <math.h>

#define N_    64
#define C_    128
#define K_    64
#define P_    4096
#define ALPHA_ 50.0f
#define EPS_  1e-12f

typedef unsigned long long ull;

// ---------------- scratch ----------------
__device__ float g_Wn[C_ * K_];
__device__ float g_partial[N_ * 4 * K_ * C_];   // [n][ps][k][c]  (8MB)
__device__ float g_sasum[N_ * 4 * K_];          // [n][ps][k]

// ---------------- f32x2 helpers ----------------
__device__ __forceinline__ ull pk2(float a, float b) {
    ull r;
    asm("mov.b64 %0, {%1, %2};" : "=l"(r) : "r"(__float_as_uint(a)), "r"(__float_as_uint(b)));
    return r;
}
__device__ __forceinline__ void upk2(ull v, float& a, float& b) {
    unsigned int x, y;
    asm("mov.b64 {%0, %1}, %2;" : "=r"(x), "=r"(y) : "l"(v));
    a = __uint_as_float(x); b = __uint_as_float(y);
}
#define FMA2_(d, a, b) asm("fma.rn.f32x2 %0, %1, %2, %3;" : "=l"(d) : "l"(a), "l"(b), "l"(d))

// ---------------- kernel 0: column-normalize W (parallel) ----------------
// grid = 64 (one block per k), block = 128 (one thread per c)
__global__ __launch_bounds__(128) void wn_kernel(const float* __restrict__ W) {
    __shared__ float red[4];
    const int k = blockIdx.x, c = threadIdx.x;
    float v = W[c * K_ + k];
    float ss = v * v;
    ss += __shfl_xor_sync(0xffffffffu, ss, 1);
    ss += __shfl_xor_sync(0xffffffffu, ss, 2);
    ss += __shfl_xor_sync(0xffffffffu, ss, 4);
    ss += __shfl_xor_sync(0xffffffffu, ss, 8);
    ss += __shfl_xor_sync(0xffffffffu, ss, 16);
    if ((c & 31) == 0) red[c >> 5] = ss;
    __syncthreads();
    float tot = red[0] + red[1] + red[2] + red[3];
    float inv = 1.f / fmaxf(sqrtf(tot), EPS_);
    g_Wn[c * K_ + k] = v * inv;
}

// ---------------- fused mega kernel ----------------
// grid (4, 64) = 256 blocks -> single wave at 2 blocks/SM.
// Block = (n, 1024-pixel slice), 16 subtiles of 64 pixels.
#define XF_STR 68
#define SA_STR 68

__global__ __launch_bounds__(256, 2) void kMega(const float* __restrict__ x,
                                                const float* __restrict__ bias,
                                                float* __restrict__ logits_out) {
    extern __shared__ float sm[];
    float* ws  = sm;                       // [c][k]      8192
    float* xf  = sm + C_ * K_;             // [c][XF_STR] 8704
    float* sas = xf + C_ * XF_STR;         // [k][SA_STR] 4352
    float* bs  = sas + K_ * SA_STR;        // [64]

    const int tid = threadIdx.x;
    const int n   = blockIdx.y;
    const int ps  = blockIdx.x;            // 0..3, 1024 pixels each

    for (int i = tid; i < C_ * K_; i += 256) ws[i] = g_Wn[i];
    if (tid < 64) bs[tid] = bias[tid];

    const int pq  = tid & 15, cq = tid >> 4;   // loader
    const int pg  = tid & 15, kg = tid >> 4;   // GEMM1
    const int kg2 = tid & 15, cg = tid >> 4;   // GEMM2: k = kg2 + 16*kq, c = cg*8+m
    const int pN  = tid >> 2, qN = tid & 3;    // normalize / softmax
    const int kS  = tid & 63, part = tid >> 6; // sasum

    ull acc2[4][8];
    #pragma unroll
    for (int a = 0; a < 4; ++a)
        #pragma unroll
        for (int b = 0; b < 8; ++b) acc2[a][b] = 0ull;
    float sasum_reg = 0.f;

    const float* xbase = x + (size_t)n * C_ * P_ + ps * 1024;
    float* lb = logits_out + (size_t)n * K_ * P_ + ps * 1024;

    __syncthreads();

    for (int sub = 0; sub < 16; ++sub) {
        const int p0 = sub * 64;

        // ---- load raw x tile [c][p] (coalesced float4) ----
        {
            const float* xp = xbase + p0 + pq * 4;
            #pragma unroll
            for (int i = 0; i < 8; ++i) {
                int c = cq + 16 * i;
                float4 v = *(const float4*)(xp + (size_t)c * P_);
                *(float4*)(xf + c * XF_STR + pq * 4) = v;
            }
        }
        __syncthreads();

        // ---- per-pixel L2 normalize in place (4 threads / pixel) ----
        {
            float vals[32]; float ss = 0.f;
            #pragma unroll
            for (int i = 0; i < 32; ++i) {
                float v = xf[(qN + 4 * i) * XF_STR + pN];
                vals[i] = v; ss = fmaf(v, v, ss);
            }
            ss += __shfl_xor_sync(0xffffffffu, ss, 1);
            ss += __shfl_xor_sync(0xffffffffu, ss, 2);
            float inv = 1.f / fmaxf(sqrtf(ss), EPS_);
            #pragma unroll
            for (int i = 0; i < 32; ++i)
                xf[(qN + 4 * i) * XF_STR + pN] = vals[i] * inv;
        }
        __syncthreads();

        // ---- GEMM1: logits[4k x 4p], acc packed over p-pairs ----
        {
            ull a0[4], a1[4];
            #pragma unroll
            for (int kq = 0; kq < 4; ++kq) { a0[kq] = 0ull; a1[kq] = 0ull; }

            #pragma unroll 4
            for (int c = 0; c < C_; ++c) {
                ulonglong2 xp2 = *(const ulonglong2*)(xf + c * XF_STR + pg * 4);
                float4 w4 = *(const float4*)(ws + c * K_ + kg * 4);
                ull w;
                w = pk2(w4.x, w4.x); FMA2_(a0[0], w, xp2.x); FMA2_(a1[0], w, xp2.y);
                w = pk2(w4.y, w4.y); FMA2_(a0[1], w, xp2.x); FMA2_(a1[1], w, xp2.y);
                w = pk2(w4.z, w4.z); FMA2_(a0[2], w, xp2.x); FMA2_(a1[2], w, xp2.y);
                w = pk2(w4.w, w4.w); FMA2_(a0[3], w, xp2.x); FMA2_(a1[3], w, xp2.y);
            }

            #pragma unroll
            for (int kq = 0; kq < 4; ++kq) {
                float l0, l1, l2, l3;
                upk2(a0[kq], l0, l1);
                upk2(a1[kq], l2, l3);
                int k = kg * 4 + kq;
                float4 v4 = make_float4(l0, l1, l2, l3);
                *(float4*)(lb + (size_t)k * P_ + p0 + pg * 4) = v4;
                *(float4*)(sas + k * SA_STR + pg * 4) = v4;
            }
        }
        __syncthreads();

        // ---- softmax over k per pixel (4 threads / pixel), in place on sas ----
        {
            float lv[16];
            float m = -3.4e38f;
            #pragma unroll
            for (int i = 0; i < 16; ++i) {
                int k = qN + 4 * i;
                float t = (sas[k * SA_STR + pN] + bs[k]) * ALPHA_;
                lv[i] = t; m = fmaxf(m, t);
            }
            m = fmaxf(m, __shfl_xor_sync(0xffffffffu, m, 1));
            m = fmaxf(m, __shfl_xor_sync(0xffffffffu, m, 2));
            float s = 0.f;
            #pragma unroll
            for (int i = 0; i < 16; ++i) {
                float e = __expf(lv[i] - m);
                lv[i] = e; s += e;
            }
            s += __shfl_xor_sync(0xffffffffu, s, 1);
            s += __shfl_xor_sync(0xffffffffu, s, 2);
            float rs = 1.f / s;
            #pragma unroll
            for (int i = 0; i < 16; ++i)
                sas[(qN + 4 * i) * SA_STR + pN] = lv[i] * rs;
        }
        __syncthreads();

        // ---- sasum partial (thread owns (part, k)) ----
        {
            float s = 0.f;
            #pragma unroll
            for (int i = 0; i < 16; ++i) s += sas[kS * SA_STR + part * 16 + i];
            sasum_reg += s;
        }

        // ---- GEMM2: acc2[4k x 8c] packed over p-parity, 32 p-pairs ----
        {
            #pragma unroll 2
            for (int j = 0; j < 32; ++j) {
                ull s0 = *(const ull*)(sas + (kg2 +  0) * SA_STR + 2 * j);
                ull s1 = *(const ull*)(sas + (kg2 + 16) * SA_STR + 2 * j);
                ull s2 = *(const ull*)(sas + (kg2 + 32) * SA_STR + 2 * j);
                ull s3 = *(const ull*)(sas + (kg2 + 48) * SA_STR + 2 * j);
                ull xv0 = *(const ull*)(xf + (cg * 8 + 0) * XF_STR + 2 * j);
                ull xv1 = *(const ull*)(xf + (cg * 8 + 1) * XF_STR + 2 * j);
                ull xv2 = *(const ull*)(xf + (cg * 8 + 2) * XF_STR + 2 * j);
                ull xv3 = *(const ull*)(xf + (cg * 8 + 3) * XF_STR + 2 * j);
                ull xv4 = *(const ull*)(xf + (cg * 8 + 4) * XF_STR + 2 * j);
                ull xv5 = *(const ull*)(xf + (cg * 8 + 5) * XF_STR + 2 * j);
                ull xv6 = *(const ull*)(xf + (cg * 8 + 6) * XF_STR + 2 * j);
                ull xv7 = *(const ull*)(xf + (cg * 8 + 7) * XF_STR + 2 * j);
                FMA2_(acc2[0][0], s0, xv0); FMA2_(acc2[0][1], s0, xv1);
                FMA2_(acc2[0][2], s0, xv2); FMA2_(acc2[0][3], s0, xv3);
                FMA2_(acc2[0][4], s0, xv4); FMA2_(acc2[0][5], s0, xv5);
                FMA2_(acc2[0][6], s0, xv6); FMA2_(acc2[0][7], s0, xv7);
                FMA2_(acc2[1][0], s1, xv0); FMA2_(acc2[1][1], s1, xv1);
                FMA2_(acc2[1][2], s1, xv2); FMA2_(acc2[1][3], s1, xv3);
                FMA2_(acc2[1][4], s1, xv4); FMA2_(acc2[1][5], s1, xv5);
                FMA2_(acc2[1][6], s1, xv6); FMA2_(acc2[1][7], s1, xv7);
                FMA2_(acc2[2][0], s2, xv0); FMA2_(acc2[2][1], s2, xv1);
                FMA2_(acc2[2][2], s2, xv2); FMA2_(acc2[2][3], s2, xv3);
                FMA2_(acc2[2][4], s2, xv4); FMA2_(acc2[2][5], s2, xv5);
                FMA2_(acc2[2][6], s2, xv6); FMA2_(acc2[2][7], s2, xv7);
                FMA2_(acc2[3][0], s3, xv0); FMA2_(acc2[3][1], s3, xv1);
                FMA2_(acc2[3][2], s3, xv2); FMA2_(acc2[3][3], s3, xv3);
                FMA2_(acc2[3][4], s3, xv4); FMA2_(acc2[3][5], s3, xv5);
                FMA2_(acc2[3][6], s3, xv6); FMA2_(acc2[3][7], s3, xv7);
            }
        }
        __syncthreads();
    }

    // ---- write GEMM2 split partials (fold p-parity halves) ----
    {
        float* pp = g_partial + ((size_t)(n * 4 + ps) * K_) * C_;
        #pragma unroll
        for (int kq = 0; kq < 4; ++kq) {
            int k = kg2 + 16 * kq;
            #pragma unroll
            for (int m = 0; m < 8; ++m) {
                float u0, u1;
                upk2(acc2[kq][m], u0, u1);
                pp[k * C_ + cg * 8 + m] = u0 + u1;
            }
        }
    }

    // ---- reduce sasum parts (sas region reusable after last sync) ----
    sas[part * 64 + kS] = sasum_reg;
    __syncthreads();
    if (tid < 64)
        g_sasum[(n * 4 + ps) * 64 + tid] =
            sas[tid] + sas[64 + tid] + sas[128 + tid] + sas[192 + tid];
}

// ---------------- kernel D: combine + subtract + intra-norm + global/8 ----------------
__global__ __launch_bounds__(128) void kD(const float* __restrict__ W,
                                          float* __restrict__ vlad_out) {
    __shared__ float red[128];
    const int b = blockIdx.x;
    const int n = b >> 6, k = b & 63, tid = threadIdx.x;

    float sasum = 0.f;
    #pragma unroll
    for (int ps = 0; ps < 4; ++ps) sasum += g_sasum[(n * 4 + ps) * 64 + k];

    float v = 0.f;
    #pragma unroll
    for (int ps = 0; ps < 4; ++ps)
        v += g_partial[((size_t)(n * 4 + ps) * K_ + k) * C_ + tid];
    v = fmaf(-sasum, W[tid * K_ + k], v);

    red[tid] = v * v; __syncthreads();
    #pragma unroll
    for (int o = 64; o > 0; o >>= 1) { if (tid < o) red[tid] += red[tid + o]; __syncthreads(); }
    // intra-norm; global L2 over 64 unit-norm rows is exactly sqrt(64)=8
    float inv = 0.125f / fmaxf(sqrtf(red[0]), EPS_);
    vlad_out[((size_t)n * K_ + k) * C_ + tid] = v * inv;
}

// ---------------- launch ----------------
extern "C" void kernel_launch(void* const* d_in, const int* in_sizes, int n_in,
                              void* d_out, int out_size) {
    const float* x    = (const float*)d_in[0];
    const float* W    = (const float*)d_in[1];
    const float* bias = (const float*)d_in[2];
    float* out        = (float*)d_out;
    float* vlad_out   = out;                               // [64, 8192]
    float* logits_out = out + (size_t)N_ * K_ * C_;        // [64, 64, 4096]

    const int smemM = (C_ * K_ + C_ * XF_STR + K_ * SA_STR + 64) * (int)sizeof(float);
    static bool attr_set = false;
    if (!attr_set) {
        cudaFuncSetAttribute(kMega, cudaFuncAttributeMaxDynamicSharedMemorySize, smemM);
        attr_set = true;
    }

    wn_kernel<<<K_, 128>>>(W);

    dim3 gM(4, N_);
    kMega<<<gM, 256, smemM>>>(x, bias, logits_out);

    kD<<<N_ * K_, 128>>>(W, vlad_out);
}